// round 1
// baseline (speedup 1.0000x reference)
#include <cuda_runtime.h>
#include <cstdint>
#include <cstddef>

#define T_TOK 2048
#define LM    4096
#define VIS   32768
#define FF    1024
#define NB    16

// ---------------- scratch (device globals; no allocations allowed) ----------
__device__ float g_yv_part[64][NB][FF];   // split-K partials for vision GEMM (4 MB)
__device__ float g_yv[NB][FF];            // vision projection per batch [16,1024]
__device__ float g_h0[T_TOK][FF];         // ping
__device__ float g_h1[T_TOK][FF];         // pong
__device__ int   g_tbi[T_TOK];            // normalized int32 token_batch_idx

__device__ __forceinline__ uint32_t to_tf32(float x) {
    uint32_t y;
    asm("cvt.rna.tf32.f32 %0, %1;" : "=r"(y) : "f"(x));
    return y;
}

// ---------------- idx dtype resolve (int64 vs int32, decided on-device) -----
__global__ void resolve_idx_kernel(const int* __restrict__ raw) {
    __shared__ int red[32];
    __shared__ int is64;
    int tid = threadIdx.x;              // 1024 threads, 1 block
    // Sum odd int32 words among first 2048 int32s (safe for both dtypes).
    // If the buffer is int64 (values < 16), every odd word is 0 -> sum == 0.
    int local = raw[2 * tid + 1];
    #pragma unroll
    for (int o = 16; o; o >>= 1) local += __shfl_down_sync(~0u, local, o);
    if ((tid & 31) == 0) red[tid >> 5] = local;
    __syncthreads();
    if (tid == 0) {
        int s = 0;
        for (int w = 0; w < 32; w++) s += red[w];
        is64 = (s == 0);
    }
    __syncthreads();
    int f = is64;
    for (int i = tid; i < T_TOK; i += 1024)
        g_tbi[i] = f ? raw[2 * i] : raw[i];
}

// ---------------- vision GEMM: yv[16,1024] = vis_flat[16,32768] @ W1_vis ----
// Split-K (64 chunks of 512), rank-16 update per column, fp32, deterministic.
__global__ void __launch_bounds__(256) vis_gemm_partial(
    const float* __restrict__ vis, const float* __restrict__ W1) {
    const int n  = blockIdx.x * 256 + threadIdx.x;  // column 0..1023 (grid.x=4)
    const int kc = blockIdx.y;                      // 0..63
    const int k0 = kc * 512;
    __shared__ float4 vs4[NB][32];                  // 16 x 128 fp32 chunk of vis
    float acc[NB];
    #pragma unroll
    for (int b = 0; b < NB; b++) acc[b] = 0.f;

    for (int ks = 0; ks < 512; ks += 128) {
        __syncthreads();
        for (int i = threadIdx.x; i < NB * 32; i += 256) {
            int b = i >> 5, q = i & 31;
            vs4[b][q] = *(const float4*)&vis[(size_t)b * VIS + k0 + ks + q * 4];
        }
        __syncthreads();
        const float* Wp = &W1[(size_t)(k0 + ks) * FF + n];
        #pragma unroll 4
        for (int kk = 0; kk < 128; kk += 4) {
            float w0 = Wp[(size_t)(kk + 0) * FF];
            float w1 = Wp[(size_t)(kk + 1) * FF];
            float w2 = Wp[(size_t)(kk + 2) * FF];
            float w3 = Wp[(size_t)(kk + 3) * FF];
            #pragma unroll
            for (int b = 0; b < NB; b++) {
                float4 v = vs4[b][kk >> 2];
                acc[b] = fmaf(v.x, w0, acc[b]);
                acc[b] = fmaf(v.y, w1, acc[b]);
                acc[b] = fmaf(v.z, w2, acc[b]);
                acc[b] = fmaf(v.w, w3, acc[b]);
            }
        }
    }
    #pragma unroll
    for (int b = 0; b < NB; b++) g_yv_part[kc][b][n] = acc[b];
}

__global__ void vis_reduce() {
    int i = blockIdx.x * blockDim.x + threadIdx.x;  // 16384 threads
    int b = i >> 10, n = i & 1023;
    float s = 0.f;
    #pragma unroll 8
    for (int c = 0; c < 64; c++) s += g_yv_part[c][b][n];
    g_yv[b][n] = s;
}

// ---------------- main GEMM: C = relu(A[2048,K] @ Bw[K,1024] + bias (+ yv gather))
// tf32 mma.sync m16n8k8, 128x128 block tile, 8 warps (2m x 4n), 64x32 warp tile,
// K-tile 16, double-buffered smem with register-staged global prefetch.
__global__ void __launch_bounds__(256) mlp_gemm(
    const float* __restrict__ A, const float* __restrict__ Bw,
    const float* __restrict__ bias, float* __restrict__ C,
    int K, int add_vis) {
    __shared__ float As[2][128][17];
    __shared__ float Bs[2][16][132];

    const int tid  = threadIdx.x;
    const int m0   = blockIdx.y * 128, n0 = blockIdx.x * 128;
    const int warp = tid >> 5, lane = tid & 31;
    const int wm   = warp >> 2, wn = warp & 3;
    const int g    = lane >> 2, tq = lane & 3;

    float acc[4][4][4];
    #pragma unroll
    for (int mi = 0; mi < 4; mi++)
        #pragma unroll
        for (int ni = 0; ni < 4; ni++)
            #pragma unroll
            for (int q = 0; q < 4; q++) acc[mi][ni][q] = 0.f;

    const int a_row = tid >> 2, a_q = (tid & 3) * 4;   // A: rows 0..63 (+64)
    const int b_row = tid >> 5, b_q = (tid & 31) * 4;  // B: rows 0..7  (+8)

    float4 ar0, ar1, br0, br1;
    auto gload = [&](int k0) {
        ar0 = *(const float4*)&A[(size_t)(m0 + a_row) * K + k0 + a_q];
        ar1 = *(const float4*)&A[(size_t)(m0 + a_row + 64) * K + k0 + a_q];
        br0 = *(const float4*)&Bw[(size_t)(k0 + b_row) * FF + n0 + b_q];
        br1 = *(const float4*)&Bw[(size_t)(k0 + b_row + 8) * FF + n0 + b_q];
    };
    auto sstore = [&](int buf) {
        As[buf][a_row][a_q + 0] = __uint_as_float(to_tf32(ar0.x));
        As[buf][a_row][a_q + 1] = __uint_as_float(to_tf32(ar0.y));
        As[buf][a_row][a_q + 2] = __uint_as_float(to_tf32(ar0.z));
        As[buf][a_row][a_q + 3] = __uint_as_float(to_tf32(ar0.w));
        As[buf][a_row + 64][a_q + 0] = __uint_as_float(to_tf32(ar1.x));
        As[buf][a_row + 64][a_q + 1] = __uint_as_float(to_tf32(ar1.y));
        As[buf][a_row + 64][a_q + 2] = __uint_as_float(to_tf32(ar1.z));
        As[buf][a_row + 64][a_q + 3] = __uint_as_float(to_tf32(ar1.w));
        Bs[buf][b_row][b_q + 0] = __uint_as_float(to_tf32(br0.x));
        Bs[buf][b_row][b_q + 1] = __uint_as_float(to_tf32(br0.y));
        Bs[buf][b_row][b_q + 2] = __uint_as_float(to_tf32(br0.z));
        Bs[buf][b_row][b_q + 3] = __uint_as_float(to_tf32(br0.w));
        Bs[buf][b_row + 8][b_q + 0] = __uint_as_float(to_tf32(br1.x));
        Bs[buf][b_row + 8][b_q + 1] = __uint_as_float(to_tf32(br1.y));
        Bs[buf][b_row + 8][b_q + 2] = __uint_as_float(to_tf32(br1.z));
        Bs[buf][b_row + 8][b_q + 3] = __uint_as_float(to_tf32(br1.w));
    };

    gload(0);
    sstore(0);
    __syncthreads();

    const int KT = K >> 4;
    for (int kt = 0; kt < KT; kt++) {
        const int cur = kt & 1;
        if (kt + 1 < KT) gload((kt + 1) << 4);

        #pragma unroll
        for (int kk = 0; kk < 16; kk += 8) {
            uint32_t af[4][4], bf[4][2];
            #pragma unroll
            for (int mi = 0; mi < 4; mi++) {
                int r = wm * 64 + mi * 16 + g;
                af[mi][0] = __float_as_uint(As[cur][r][kk + tq]);
                af[mi][1] = __float_as_uint(As[cur][r + 8][kk + tq]);
                af[mi][2] = __float_as_uint(As[cur][r][kk + tq + 4]);
                af[mi][3] = __float_as_uint(As[cur][r + 8][kk + tq + 4]);
            }
            #pragma unroll
            for (int ni = 0; ni < 4; ni++) {
                int c = wn * 32 + ni * 8 + g;
                bf[ni][0] = __float_as_uint(Bs[cur][kk + tq][c]);
                bf[ni][1] = __float_as_uint(Bs[cur][kk + tq + 4][c]);
            }
            #pragma unroll
            for (int mi = 0; mi < 4; mi++)
                #pragma unroll
                for (int ni = 0; ni < 4; ni++)
                    asm volatile(
                        "mma.sync.aligned.m16n8k8.row.col.f32.tf32.tf32.f32 "
                        "{%0,%1,%2,%3}, {%4,%5,%6,%7}, {%8,%9}, {%0,%1,%2,%3};"
                        : "+f"(acc[mi][ni][0]), "+f"(acc[mi][ni][1]),
                          "+f"(acc[mi][ni][2]), "+f"(acc[mi][ni][3])
                        : "r"(af[mi][0]), "r"(af[mi][1]), "r"(af[mi][2]),
                          "r"(af[mi][3]), "r"(bf[ni][0]), "r"(bf[ni][1]));
        }

        if (kt + 1 < KT) sstore(cur ^ 1);
        __syncthreads();
    }

    // epilogue: + bias (+ yv[tbi[row]]) , relu, store
    #pragma unroll
    for (int mi = 0; mi < 4; mi++) {
        int r0 = m0 + wm * 64 + mi * 16 + g;
        #pragma unroll
        for (int rr = 0; rr < 2; rr++) {
            int row = r0 + rr * 8;
            const float* yrow = nullptr;
            if (add_vis) yrow = &g_yv[g_tbi[row]][0];
            #pragma unroll
            for (int ni = 0; ni < 4; ni++) {
                int col = n0 + wn * 32 + ni * 8 + tq * 2;
                float v0 = acc[mi][ni][rr * 2 + 0] + bias[col];
                float v1 = acc[mi][ni][rr * 2 + 1] + bias[col + 1];
                if (add_vis) { v0 += yrow[col]; v1 += yrow[col + 1]; }
                v0 = fmaxf(v0, 0.f);
                v1 = fmaxf(v1, 0.f);
                C[(size_t)row * FF + col]     = v0;
                C[(size_t)row * FF + col + 1] = v1;
            }
        }
    }
}

// ---------------- head: out[2048,6] = h4 @ W5 + b5 (warp per token) ---------
__global__ void __launch_bounds__(256) head_kernel(
    const float* __restrict__ H, const float* __restrict__ W5,
    const float* __restrict__ b5, float* __restrict__ out) {
    int t    = blockIdx.x * 8 + (threadIdx.x >> 5);
    int lane = threadIdx.x & 31;
    float a0 = 0, a1 = 0, a2 = 0, a3 = 0, a4 = 0, a5 = 0;
    const float* h = H + (size_t)t * FF;
    for (int k = lane; k < FF; k += 32) {
        float hv = h[k];
        const float2 w01 = *(const float2*)&W5[(size_t)k * 6 + 0];
        const float2 w23 = *(const float2*)&W5[(size_t)k * 6 + 2];
        const float2 w45 = *(const float2*)&W5[(size_t)k * 6 + 4];
        a0 = fmaf(hv, w01.x, a0);
        a1 = fmaf(hv, w01.y, a1);
        a2 = fmaf(hv, w23.x, a2);
        a3 = fmaf(hv, w23.y, a3);
        a4 = fmaf(hv, w45.x, a4);
        a5 = fmaf(hv, w45.y, a5);
    }
    #pragma unroll
    for (int o = 16; o; o >>= 1) {
        a0 += __shfl_down_sync(~0u, a0, o);
        a1 += __shfl_down_sync(~0u, a1, o);
        a2 += __shfl_down_sync(~0u, a2, o);
        a3 += __shfl_down_sync(~0u, a3, o);
        a4 += __shfl_down_sync(~0u, a4, o);
        a5 += __shfl_down_sync(~0u, a5, o);
    }
    if (lane == 0) {
        float* o = out + (size_t)t * 6;
        o[0] = a0 + b5[0];
        o[1] = a1 + b5[1];
        o[2] = a2 + b5[2];
        o[3] = a3 + b5[3];
        o[4] = a4 + b5[4];
        o[5] = a5 + b5[5];
    }
}

// ---------------- launch -----------------------------------------------------
extern "C" void kernel_launch(void* const* d_in, const int* in_sizes, int n_in,
                              void* d_out, int out_size) {
    const float* grd     = (const float*)d_in[0];
    const float* vis     = (const float*)d_in[1];
    const int*   tbi_raw = (const int*)d_in[2];
    const float* W1 = (const float*)d_in[3];
    const float* b1 = (const float*)d_in[4];
    const float* W2 = (const float*)d_in[5];
    const float* b2 = (const float*)d_in[6];
    const float* W3 = (const float*)d_in[7];
    const float* b3 = (const float*)d_in[8];
    const float* W4 = (const float*)d_in[9];
    const float* b4 = (const float*)d_in[10];
    const float* W5 = (const float*)d_in[11];
    const float* b5 = (const float*)d_in[12];
    float* out = (float*)d_out;

    float *h0, *h1;
    cudaGetSymbolAddress((void**)&h0, g_h0);
    cudaGetSymbolAddress((void**)&h1, g_h1);

    resolve_idx_kernel<<<1, 1024>>>(tbi_raw);
    vis_gemm_partial<<<dim3(4, 64), 256>>>(vis, W1);
    vis_reduce<<<64, 256>>>();
    // layer 1: language part of W1 + gathered vision projection + b1, relu
    mlp_gemm<<<dim3(8, 16), 256>>>(grd, W1 + (size_t)VIS * FF, b1, h0, LM, 1);
    mlp_gemm<<<dim3(8, 16), 256>>>(h0, W2, b2, h1, FF, 0);
    mlp_gemm<<<dim3(8, 16), 256>>>(h1, W3, b3, h0, FF, 0);
    mlp_gemm<<<dim3(8, 16), 256>>>(h0, W4, b4, h1, FF, 0);
    head_kernel<<<256, 256>>>(h1, W5, b5, out);
}